// round 15
// baseline (speedup 1.0000x reference)
#include <cuda_runtime.h>
#include <cuda_fp16.h>
#include <cstdint>
#include <cfloat>

// VQ R15: 1-pass fp16 hi screen (R8 shape) + global top-2 certification.
// If approx (best - snd) > 2*eps(pixel): approx argmax == exact argmin, done.
// Else (rare): warp-cooperative exact fp32 rescore of all 512 codes.

#define D    64
#define K    512
#define MT   128     // pixels per CTA
#define T    512     // threads per CTA (16 warps)

// SMEM layout (bytes)
#define SX_OFF    0                       // x tile fp32 [d][m]=[64][128]  32KB
#define BA_OFF    32768                   // codebook hi fp16 [512][128B]  64KB
#define SHES_OFF  98304                   // 512 f32
#define SAPX_OFF  100352                  // 128 u64 (ord(best)|511-idx)
#define SSND_OFF  101376                  // 128 u32 ord(second-best)
#define SNORM_OFF 101888                  // 128 f32 ||x||^2
#define SBN_OFF   102400                  // 128 f32 ||b_x||^2
#define SBI_OFF   102912                  // 128 int final index
#define CNT_OFF   103424                  // int ambiguous count (+pad 16)
#define LIST_OFF  103440                  // 128 int ambiguous pixels
#define SMEM_SZ   103952

__device__ __half g_ea[K * D];   // fp16 hi split, permuted+swizzled rows
__device__ float  g_hes[K];      // 0.5*||e||^2
__device__ int    g_man = 0;     // max_k ||a_e,k|| (float bits)
__device__ int    g_mbn = 0;     // max_k ||b_e,k|| (float bits)

// ---------------- helpers ----------------
__device__ __forceinline__ uint32_t smem_u32(const void* p) {
    uint32_t a;
    asm("{ .reg .u64 t; cvta.to.shared.u64 t, %1; cvt.u32.u64 %0, t; }" : "=r"(a) : "l"(p));
    return a;
}
#define MMA_F16(c, a0, a1, a2, a3, b0, b1)                                       \
    asm volatile("mma.sync.aligned.m16n8k16.row.col.f32.f16.f16.f32 "            \
        "{%0,%1,%2,%3},{%4,%5,%6,%7},{%8,%9},{%0,%1,%2,%3};"                     \
        : "+f"((c)[0]), "+f"((c)[1]), "+f"((c)[2]), "+f"((c)[3])                  \
        : "r"(a0), "r"(a1), "r"(a2), "r"(a3), "r"(b0), "r"(b1))

__device__ __forceinline__ void cp16(uint32_t dst, const void* src) {
    asm volatile("cp.async.cg.shared.global [%0], [%1], 16;" :: "r"(dst), "l"(src) : "memory");
}
#define CP_COMMIT() asm volatile("cp.async.commit_group;" ::: "memory")
#define CP_WAIT(n)  asm volatile("cp.async.wait_group %0;" :: "n"(n) : "memory")

__device__ __forceinline__ uint32_t pack2(__half x, __half y) {
    __half2 h = __halves2half2(x, y);
    return *(uint32_t*)&h;
}
__device__ __forceinline__ unsigned ord_enc(float f) {
    unsigned u = __float_as_uint(f);
    return (u & 0x80000000u) ? ~u : (u | 0x80000000u);
}
__device__ __forceinline__ float ord_dec(unsigned u) {
    return __uint_as_float((u & 0x80000000u) ? (u & 0x7fffffffu) : ~u);
}

// ---------------- prep: hi codebook (permuted+swizzled), norms ----------------
__global__ void vq_prep(const float* __restrict__ embed) {
    int k = blockIdx.x, d = threadIdx.x;
    float v = embed[k * D + d];
    __half a = __float2half_rn(v);
    float af = __half2float(a);
    float bf = v - af;
    int g = d >> 5, kk = d & 31;
    int rr = (kk >> 1) & 3, h = (kk >> 3) & 1, c = (kk >> 4) & 1, par = kk & 1;
    int slot = ((g << 2) + rr + ((k & 1) << 2)) & 7;
    g_ea[k * 64 + slot * 8 + ((c << 1) + h) * 2 + par] = a;
    float s = v * v, sa = af * af, sb2 = bf * bf;
    #pragma unroll
    for (int o = 16; o > 0; o >>= 1) {
        s   += __shfl_down_sync(0xffffffffu, s, o);
        sa  += __shfl_down_sync(0xffffffffu, sa, o);
        sb2 += __shfl_down_sync(0xffffffffu, sb2, o);
    }
    __shared__ float ws[6];
    if ((d & 31) == 0) {
        ws[(d >> 5) * 3 + 0] = s;
        ws[(d >> 5) * 3 + 1] = sa;
        ws[(d >> 5) * 3 + 2] = sb2;
    }
    __syncthreads();
    if (d == 0) {
        g_hes[k] = 0.5f * (ws[0] + ws[3]);
        atomicMax(&g_man, __float_as_int(sqrtf(ws[1] + ws[4])));
        atomicMax(&g_mbn, __float_as_int(sqrtf(ws[2] + ws[5])));
    }
}

// exact fp32 rescore (x from SMEM broadcast, e from L2)
__device__ __forceinline__ float rescore(const float* __restrict__ embed,
                                          const float* __restrict__ sx,
                                          const float* __restrict__ shes,
                                          int p, int k) {
    const float4* er = (const float4*)(embed + (size_t)k * D);
    float s0 = 0.f, s1 = 0.f, s2 = 0.f, s3 = 0.f;
    #pragma unroll 4
    for (int i = 0; i < 16; i++) {
        float4 e4 = er[i];
        s0 = fmaf(sx[(4 * i + 0) * MT + p], e4.x, s0);
        s1 = fmaf(sx[(4 * i + 1) * MT + p], e4.y, s1);
        s2 = fmaf(sx[(4 * i + 2) * MT + p], e4.z, s2);
        s3 = fmaf(sx[(4 * i + 3) * MT + p], e4.w, s3);
    }
    return ((s0 + s1) + (s2 + s3)) - shes[k];
}

// ---------------- main ----------------
__global__ void __launch_bounds__(T, 1) vq_main(const float* __restrict__ x,
                                                const float* __restrict__ embed,
                                                float* __restrict__ outq,
                                                float* __restrict__ outi) {
    extern __shared__ __align__(1024) char smem[];
    uint32_t sb = smem_u32(smem);
    const int tid = threadIdx.x, wid = tid >> 5, lane = tid & 31;
    const int q = lane >> 2, r = lane & 3;
    const int wm = wid & 7;                  // m-group (16 pixels)
    const int wg = wid >> 3;                 // n-half (codes [0,256) / [256,512))
    const int n0 = blockIdx.x * MT;
    const int b = n0 >> 12, hw0 = n0 & 4095;

    float* sx = (float*)(smem + SX_OFF);     // [d][128]
    float* shes = (float*)(smem + SHES_OFF);
    unsigned long long* sapx = (unsigned long long*)(smem + SAPX_OFF);
    unsigned* ssnd = (unsigned*)(smem + SSND_OFF);
    float* snorm = (float*)(smem + SNORM_OFF);
    float* sbn = (float*)(smem + SBN_OFF);
    int* sbi = (int*)(smem + SBI_OFF);
    int* scnt = (int*)(smem + CNT_OFF);
    int* slist = (int*)(smem + LIST_OFF);

    // stage hi codebook (64KB)
    #pragma unroll
    for (int t = 0; t < 8; t++) {
        int c = tid + t * T;
        cp16(sb + BA_OFF + c * 16, (const char*)g_ea + c * 16);
    }
    CP_COMMIT();

    // stage x tile: sx[c][j] = x[b][c][hw0+j]
    #pragma unroll
    for (int t = 0; t < 4; t++) {
        int i = tid + t * T;
        int c = i >> 5, j4 = (i & 31) << 2;
        float4 v = *(const float4*)(x + (((size_t)(b * D + c)) << 12) + hw0 + j4);
        *(float4*)(sx + c * MT + j4) = v;
    }
    shes[tid] = g_hes[tid];
    if (tid < MT) { sapx[tid] = 0ull; ssnd[tid] = 0u; }
    if (tid == 0) *scnt = 0;
    CP_WAIT(0);
    __syncthreads();

    // A hi fragments + ||x||^2, ||b_x||^2 partials
    const int m0 = wm * 16;
    const int pa = m0 + q, pb = m0 + q + 8;
    uint32_t Aa[4][4];
    float xp0 = 0.f, xp1 = 0.f, bp0 = 0.f, bp1 = 0.f;
    #pragma unroll
    for (int cc = 0; cc < 4; cc++) {
        #pragma unroll
        for (int hh = 0; hh < 2; hh++) {
            int k = 16 * cc + 2 * r + 8 * hh;
            float f0a = sx[k * MT + pa], f1a = sx[(k + 1) * MT + pa];
            float f0b = sx[k * MT + pb], f1b = sx[(k + 1) * MT + pb];
            __half a0 = __float2half_rn(f0a), a1 = __float2half_rn(f1a);
            __half b0 = __float2half_rn(f0b), b1 = __float2half_rn(f1b);
            float r0a = f0a - __half2float(a0), r1a = f1a - __half2float(a1);
            float r0b = f0b - __half2float(b0), r1b = f1b - __half2float(b1);
            xp0 = fmaf(f0a, f0a, fmaf(f1a, f1a, xp0));
            xp1 = fmaf(f0b, f0b, fmaf(f1b, f1b, xp1));
            bp0 = fmaf(r0a, r0a, fmaf(r1a, r1a, bp0));
            bp1 = fmaf(r0b, r0b, fmaf(r1b, r1b, bp1));
            Aa[cc][2 * hh]     = pack2(a0, a1);
            Aa[cc][2 * hh + 1] = pack2(b0, b1);
        }
    }
    xp0 += __shfl_xor_sync(0xffffffffu, xp0, 1); xp0 += __shfl_xor_sync(0xffffffffu, xp0, 2);
    xp1 += __shfl_xor_sync(0xffffffffu, xp1, 1); xp1 += __shfl_xor_sync(0xffffffffu, xp1, 2);
    bp0 += __shfl_xor_sync(0xffffffffu, bp0, 1); bp0 += __shfl_xor_sync(0xffffffffu, bp0, 2);
    bp1 += __shfl_xor_sync(0xffffffffu, bp1, 1); bp1 += __shfl_xor_sync(0xffffffffu, bp1, 2);
    if (r == 0 && wg == 0) {
        snorm[pa] = xp0; snorm[pb] = xp1;
        sbn[pa] = bp0;   sbn[pb] = bp1;
    }

    // ---- single screen pass: MMA + top-2 per (row, 64-code lane slice) ----
    float b0v = -FLT_MAX, s0v = -FLT_MAX;
    float b1v = -FLT_MAX, s1v = -FLT_MAX;
    int k0i = 0, k1i = 0;

    #pragma unroll 1
    for (int tg = 0; tg < 8; tg++) {
        const int t0 = wg * 32 + tg * 4;
        float acc[4][4];
        #pragma unroll
        for (int j = 0; j < 4; j++)
            #pragma unroll
            for (int c = 0; c < 4; c++) acc[j][c] = 0.0f;

        #pragma unroll
        for (int j = 0; j < 4; j++) {
            int n = (t0 + j) * 8 + q;
            const char* rowa = smem + BA_OFF + n * 128;
            int so = r + ((n & 1) << 2);
            uint4 va0 = *(const uint4*)(rowa + (so & 7) * 16);
            uint4 va1 = *(const uint4*)(rowa + ((so + 4) & 7) * 16);
            MMA_F16(acc[j], Aa[0][0], Aa[0][1], Aa[0][2], Aa[0][3], va0.x, va0.y);
            MMA_F16(acc[j], Aa[1][0], Aa[1][1], Aa[1][2], Aa[1][3], va0.z, va0.w);
            MMA_F16(acc[j], Aa[2][0], Aa[2][1], Aa[2][2], Aa[2][3], va1.x, va1.y);
            MMA_F16(acc[j], Aa[3][0], Aa[3][1], Aa[3][2], Aa[3][3], va1.z, va1.w);
        }
        #pragma unroll
        for (int j = 0; j < 4; j++) {
            int cb = (t0 + j) * 8 + 2 * r;
            float h0 = shes[cb], h1 = shes[cb + 1];
            {
                float v0 = acc[j][0] - h0, v1 = acc[j][1] - h1;
                float pm = fmaxf(v0, v1), pn = fminf(v0, v1);
                int kp = (v0 >= v1) ? cb : cb + 1;
                bool pr = pm > b0v;
                s0v = pr ? fmaxf(b0v, pn) : fmaxf(s0v, pm);
                k0i = pr ? kp : k0i;
                b0v = fmaxf(b0v, pm);
            }
            {
                float v0 = acc[j][2] - h0, v1 = acc[j][3] - h1;
                float pm = fmaxf(v0, v1), pn = fminf(v0, v1);
                int kp = (v0 >= v1) ? cb : cb + 1;
                bool pr = pm > b1v;
                s1v = pr ? fmaxf(b1v, pn) : fmaxf(s1v, pm);
                k1i = pr ? kp : k1i;
                b1v = fmaxf(b1v, pm);
            }
        }
    }

    // merge top-2 across the 4 r-lanes (values exact; ties -> snd=best, safe)
    #pragma unroll
    for (int off = 1; off <= 2; off <<= 1) {
        float ob0 = __shfl_xor_sync(0xffffffffu, b0v, off);
        float os0 = __shfl_xor_sync(0xffffffffu, s0v, off);
        int   ok0 = __shfl_xor_sync(0xffffffffu, k0i, off);
        float ob1 = __shfl_xor_sync(0xffffffffu, b1v, off);
        float os1 = __shfl_xor_sync(0xffffffffu, s1v, off);
        int   ok1 = __shfl_xor_sync(0xffffffffu, k1i, off);
        float ns0 = fmaxf(fmaxf(s0v, os0), fminf(b0v, ob0));
        float ns1 = fmaxf(fmaxf(s1v, os1), fminf(b1v, ob1));
        if (ob0 > b0v || (ob0 == b0v && ok0 < k0i)) { b0v = ob0; k0i = ok0; }
        if (ob1 > b1v || (ob1 == b1v && ok1 < k1i)) { b1v = ob1; k1i = ok1; }
        s0v = ns0; s1v = ns1;
    }
    unsigned long long pk0 = ((unsigned long long)ord_enc(b0v) << 32) | (unsigned)(K - 1 - k0i);
    unsigned long long pk1 = ((unsigned long long)ord_enc(b1v) << 32) | (unsigned)(K - 1 - k1i);
    if (r == 0) { atomicMax(&sapx[pa], pk0); atomicMax(&sapx[pb], pk1); }
    __syncthreads();
    // cross-warp second-best: winner warp contributes its snd, loser its best
    if (r == 0) {
        float c0 = (sapx[pa] == pk0) ? s0v : b0v;
        float c1 = (sapx[pb] == pk1) ? s1v : b1v;
        atomicMax(&ssnd[pa], ord_enc(c0));
        atomicMax(&ssnd[pb], ord_enc(c1));
    }
    __syncthreads();

    // ---- certify per pixel: gap > 2*eps => approx winner is exact ----
    if (tid < MT) {
        int p = tid;
        unsigned long long g = sapx[p];
        float bestv = ord_dec((unsigned)(g >> 32));
        int   besti = (K - 1) - (int)(g & 0xffffffffull);
        float sndv = ord_dec(ssnd[p]);
        float xn = sqrtf(snorm[p]), bxn = sqrtf(sbn[p]);
        float man = __int_as_float(g_man), mbn = __int_as_float(g_mbn);
        float eps = 1.02f * ((xn + 2.0f * bxn) * mbn + bxn * man) + 1e-3f;
        if (bestv - sndv > 2.0f * eps) {
            sbi[p] = besti;                       // certified, no rescore
        } else {
            slist[atomicAdd(scnt, 1)] = p;        // ambiguous -> full rescore
        }
    }
    __syncthreads();

    // ---- warp-cooperative exact rescore of ambiguous pixels ----
    {
        int cnt = *scnt;
        for (int e = wid; e < cnt; e += 16) {
            int p = slist[e];
            float bs = -FLT_MAX;
            int bi = K;
            #pragma unroll 1
            for (int j = 0; j < 16; j++) {
                int k = lane + 32 * j;
                float s = rescore(embed, sx, shes, p, k);
                if (s > bs || (s == bs && k < bi)) { bs = s; bi = k; }
            }
            #pragma unroll
            for (int off = 16; off > 0; off >>= 1) {
                float os = __shfl_xor_sync(0xffffffffu, bs, off);
                int   oi = __shfl_xor_sync(0xffffffffu, bi, off);
                if (os > bs || (os == bs && oi < bi)) { bs = os; bi = oi; }
            }
            if (lane == 0) sbi[p] = bi;
        }
    }
    __syncthreads();

    // outputs: gathered codebook rows (NHWC) + indices (float)
    #pragma unroll
    for (int t = 0; t < 4; t++) {
        int i = tid + t * T;
        int j = i >> 4, c4 = i & 15;
        int idx = sbi[j];
        float4 v = *(const float4*)(embed + idx * D + (c4 << 2));
        *(float4*)(outq + ((size_t)(n0 + j)) * D + (c4 << 2)) = v;
    }
    if (outi && tid < MT) outi[n0 + tid] = (float)sbi[tid];
}

// ---------------------------------------------------------------------------
extern "C" void kernel_launch(void* const* d_in, const int* in_sizes, int n_in,
                              void* d_out, int out_size) {
    const float* x = (const float*)d_in[0];
    const float* embed = (const float*)d_in[1];
    float* out = (float*)d_out;

    const int N = in_sizes[0] / D;
    float* outi = nullptr;
    if (out_size >= N * D + N) outi = out + (size_t)N * D;

    cudaFuncSetAttribute(vq_main, cudaFuncAttributeMaxDynamicSharedMemorySize, SMEM_SZ);
    vq_prep<<<K, D>>>(embed);
    vq_main<<<N / MT, T, SMEM_SZ>>>(x, embed, out, outi);
}

// round 16
// speedup vs baseline: 2.6968x; 2.6968x over previous
#include <cuda_runtime.h>
#include <cuda_fp16.h>
#include <cstdint>
#include <cfloat>

// VQ R16: single fp16 hi-pass screen (R8 shape) + per-slice top-2 certificate
// + LIST-BASED exact resolution (no inline rescan -> no register spills).

#define D    64
#define K    512
#define MT   128     // pixels per CTA
#define T    512     // threads per CTA (16 warps)

// SMEM layout (bytes)
#define SX_OFF    0                       // x tile fp32 [d][m]=[64][128]  32KB
#define BA_OFF    32768                   // codebook hi fp16 [512][128B]  64KB
#define SHES_OFF  98304                   // 512 f32
#define SAPX_OFF  100352                  // 128 u32 ordered approx-max
#define SBEST_OFF 100864                  // 128 u64 exact best
#define CNT_OFF   101888                  // [0]=normal count, [1]=rescan count
#define LISTN_OFF 101904                  // 1024 u32 (row<<16|code)
#define LISTR_OFF 106000                  // 1024 u32 (row<<16|wg<<2|r)
#define SMEM_SZ   110096

__device__ __half g_ea[K * D];   // fp16 hi split, permuted+swizzled rows
__device__ float  g_hes[K];      // 0.5*||e||^2
__device__ int    g_mhbits = 0;  // max hes as int bits

// ---------------- helpers ----------------
__device__ __forceinline__ uint32_t smem_u32(const void* p) {
    uint32_t a;
    asm("{ .reg .u64 t; cvta.to.shared.u64 t, %1; cvt.u32.u64 %0, t; }" : "=r"(a) : "l"(p));
    return a;
}
#define MMA_F16(c, a0, a1, a2, a3, b0, b1)                                       \
    asm volatile("mma.sync.aligned.m16n8k16.row.col.f32.f16.f16.f32 "            \
        "{%0,%1,%2,%3},{%4,%5,%6,%7},{%8,%9},{%0,%1,%2,%3};"                     \
        : "+f"((c)[0]), "+f"((c)[1]), "+f"((c)[2]), "+f"((c)[3])                  \
        : "r"(a0), "r"(a1), "r"(a2), "r"(a3), "r"(b0), "r"(b1))

__device__ __forceinline__ void cp16(uint32_t dst, const void* src) {
    asm volatile("cp.async.cg.shared.global [%0], [%1], 16;" :: "r"(dst), "l"(src) : "memory");
}
#define CP_COMMIT() asm volatile("cp.async.commit_group;" ::: "memory")
#define CP_WAIT(n)  asm volatile("cp.async.wait_group %0;" :: "n"(n) : "memory")

__device__ __forceinline__ uint32_t pack2(__half x, __half y) {
    __half2 h = __halves2half2(x, y);
    return *(uint32_t*)&h;
}
__device__ __forceinline__ unsigned ord_enc(float f) {
    unsigned u = __float_as_uint(f);
    return (u & 0x80000000u) ? ~u : (u | 0x80000000u);
}
__device__ __forceinline__ float ord_dec(unsigned u) {
    return __uint_as_float((u & 0x80000000u) ? (u & 0x7fffffffu) : ~u);
}

// exact fp32 rescore: x_p . e_k - 0.5||e_k||^2
__device__ __forceinline__ float rescore(const float* __restrict__ embed,
                                          const float* __restrict__ sx,
                                          const float* __restrict__ shes,
                                          int p, int k) {
    const float4* er = (const float4*)(embed + (size_t)k * D);
    float s0 = 0.f, s1 = 0.f, s2 = 0.f, s3 = 0.f;
    #pragma unroll 4
    for (int i = 0; i < 16; i++) {
        float4 e4 = er[i];
        s0 = fmaf(sx[(4 * i + 0) * MT + p], e4.x, s0);
        s1 = fmaf(sx[(4 * i + 1) * MT + p], e4.y, s1);
        s2 = fmaf(sx[(4 * i + 2) * MT + p], e4.z, s2);
        s3 = fmaf(sx[(4 * i + 3) * MT + p], e4.w, s3);
    }
    return ((s0 + s1) + (s2 + s3)) - shes[k];
}

// ---------------- prep: hi split codebook (permuted+swizzled), half norms ----
// element d = 32g+16c+8h+2rr+par -> slot ((g<<2)+rr+((k&1)<<2))&7, idx (2c+h)*2+par
__global__ void vq_prep(const float* __restrict__ embed) {
    int k = blockIdx.x, d = threadIdx.x;
    float v = embed[k * D + d];
    __half a = __float2half_rn(v);
    int g = d >> 5, kk = d & 31;
    int rr = (kk >> 1) & 3, h = (kk >> 3) & 1, c = (kk >> 4) & 1, par = kk & 1;
    int slot = ((g << 2) + rr + ((k & 1) << 2)) & 7;
    g_ea[k * 64 + slot * 8 + ((c << 1) + h) * 2 + par] = a;
    float s = v * v;
    #pragma unroll
    for (int o = 16; o > 0; o >>= 1) s += __shfl_down_sync(0xffffffffu, s, o);
    __shared__ float ws[2];
    if ((d & 31) == 0) ws[d >> 5] = s;
    __syncthreads();
    if (d == 0) {
        float hes = 0.5f * (ws[0] + ws[1]);
        g_hes[k] = hes;
        atomicMax(&g_mhbits, __float_as_int(hes));
    }
}

// ---------------- main ----------------
__global__ void __launch_bounds__(T, 1) vq_main(const float* __restrict__ x,
                                                const float* __restrict__ embed,
                                                float* __restrict__ outq,
                                                float* __restrict__ outi) {
    extern __shared__ __align__(1024) char smem[];
    uint32_t sb = smem_u32(smem);
    const int tid = threadIdx.x, wid = tid >> 5, lane = tid & 31;
    const int q = lane >> 2, r = lane & 3;
    const int wm = wid & 7;                  // m-group (16 pixels)
    const int wg = wid >> 3;                 // n-half (codes [0,256)/[256,512))
    const int n0 = blockIdx.x * MT;
    const int b = n0 >> 12, hw0 = n0 & 4095;

    float* sx = (float*)(smem + SX_OFF);     // [d][128]
    float* shes = (float*)(smem + SHES_OFF);
    unsigned* sapx = (unsigned*)(smem + SAPX_OFF);
    unsigned long long* sbest = (unsigned long long*)(smem + SBEST_OFF);
    int* scnt = (int*)(smem + CNT_OFF);
    unsigned* listn = (unsigned*)(smem + LISTN_OFF);
    unsigned* listr = (unsigned*)(smem + LISTR_OFF);

    // stage hi codebook (64KB)
    #pragma unroll
    for (int t = 0; t < 8; t++) {
        int c = tid + t * T;
        cp16(sb + BA_OFF + c * 16, (const char*)g_ea + c * 16);
    }
    CP_COMMIT();

    // stage x tile: sx[c][j] = x[b][c][hw0+j]
    #pragma unroll
    for (int t = 0; t < 4; t++) {
        int i = tid + t * T;
        int c = i >> 5, j4 = (i & 31) << 2;
        float4 v = *(const float4*)(x + (((size_t)(b * D + c)) << 12) + hw0 + j4);
        *(float4*)(sx + c * MT + j4) = v;
    }
    shes[tid] = g_hes[tid];
    if (tid < MT) { sapx[tid] = 0u; sbest[tid] = 0ull; }
    if (tid < 2) scnt[tid] = 0;
    CP_WAIT(0);
    __syncthreads();

    // A hi fragments + ||x||^2 partials: rows m0+q, m0+q+8
    const int m0 = wm * 16;
    const int pa = m0 + q, pb = m0 + q + 8;
    uint32_t Aa[4][4];
    float xp0 = 0.f, xp1 = 0.f;
    #pragma unroll
    for (int cc = 0; cc < 4; cc++) {
        #pragma unroll
        for (int hh = 0; hh < 2; hh++) {
            int k = 16 * cc + 2 * r + 8 * hh;
            float f0a = sx[k * MT + pa], f1a = sx[(k + 1) * MT + pa];
            float f0b = sx[k * MT + pb], f1b = sx[(k + 1) * MT + pb];
            xp0 = fmaf(f0a, f0a, fmaf(f1a, f1a, xp0));
            xp1 = fmaf(f0b, f0b, fmaf(f1b, f1b, xp1));
            Aa[cc][2 * hh]     = pack2(__float2half_rn(f0a), __float2half_rn(f1a));
            Aa[cc][2 * hh + 1] = pack2(__float2half_rn(f0b), __float2half_rn(f1b));
        }
    }
    xp0 += __shfl_xor_sync(0xffffffffu, xp0, 1);
    xp0 += __shfl_xor_sync(0xffffffffu, xp0, 2);
    xp1 += __shfl_xor_sync(0xffffffffu, xp1, 1);
    xp1 += __shfl_xor_sync(0xffffffffu, xp1, 2);

    // ---- single screen pass: MMA + top-2 per (row, 64-code thread slice) ----
    float best0 = -FLT_MAX, snd0 = -FLT_MAX;
    float best1 = -FLT_MAX, snd1 = -FLT_MAX;
    int bk0 = 0, bk1 = 0;

    #pragma unroll 1
    for (int tg = 0; tg < 8; tg++) {
        const int t0 = wg * 32 + tg * 4;
        float acc[4][4];
        #pragma unroll
        for (int j = 0; j < 4; j++)
            #pragma unroll
            for (int c = 0; c < 4; c++) acc[j][c] = 0.0f;

        #pragma unroll
        for (int j = 0; j < 4; j++) {
            int n = (t0 + j) * 8 + q;
            const char* rowa = smem + BA_OFF + n * 128;
            int so = r + ((n & 1) << 2);
            uint4 va0 = *(const uint4*)(rowa + (so & 7) * 16);
            uint4 va1 = *(const uint4*)(rowa + ((so + 4) & 7) * 16);
            MMA_F16(acc[j], Aa[0][0], Aa[0][1], Aa[0][2], Aa[0][3], va0.x, va0.y);
            MMA_F16(acc[j], Aa[1][0], Aa[1][1], Aa[1][2], Aa[1][3], va0.z, va0.w);
            MMA_F16(acc[j], Aa[2][0], Aa[2][1], Aa[2][2], Aa[2][3], va1.x, va1.y);
            MMA_F16(acc[j], Aa[3][0], Aa[3][1], Aa[3][2], Aa[3][3], va1.z, va1.w);
        }
        #pragma unroll
        for (int j = 0; j < 4; j++) {
            int cb = (t0 + j) * 8 + 2 * r;
            float h0 = shes[cb], h1 = shes[cb + 1];
            {
                float v0 = acc[j][0] - h0, v1 = acc[j][1] - h1;
                float pm = fmaxf(v0, v1), pn = fminf(v0, v1);
                int kp = (v0 >= v1) ? cb : cb + 1;
                bool pr = pm > best0;
                snd0 = pr ? fmaxf(best0, pn) : fmaxf(snd0, pm);
                bk0 = pr ? kp : bk0;
                best0 = fmaxf(best0, pm);
            }
            {
                float v0 = acc[j][2] - h0, v1 = acc[j][3] - h1;
                float pm = fmaxf(v0, v1), pn = fminf(v0, v1);
                int kp = (v0 >= v1) ? cb : cb + 1;
                bool pr = pm > best1;
                snd1 = pr ? fmaxf(best1, pn) : fmaxf(snd1, pm);
                bk1 = pr ? kp : bk1;
                best1 = fmaxf(best1, pm);
            }
        }
    }
    atomicMax(&sapx[pa], ord_enc(best0));
    atomicMax(&sapx[pb], ord_enc(best1));
    __syncthreads();

    // ---- per-slice certified push (tiny; no rescoring here) ----
    {
        float maxEn = sqrtf(2.0f * __int_as_float(g_mhbits));
        #pragma unroll
        for (int i = 0; i < 2; i++) {
            int row   = i ? pb : pa;
            float bst = i ? best1 : best0;
            float sn  = i ? snd1 : snd0;
            int   bk  = i ? bk1 : bk0;
            float xn2 = i ? xp1 : xp0;
            float smax = ord_dec(sapx[row]);
            float thr = smax - (2.2e-3f * sqrtf(xn2) * maxEn + 1e-5f);
            if (bst >= thr) {
                if (sn >= thr) {
                    int pos = atomicAdd(&scnt[1], 1);
                    listr[pos] = ((unsigned)row << 16) | (unsigned)((wg << 2) | r);
                } else {
                    int pos = atomicAdd(&scnt[0], 1);
                    listn[pos] = ((unsigned)row << 16) | (unsigned)bk;
                }
            }
        }
    }
    __syncthreads();

    // ---- exact resolution from lists ----
    {
        int cntn = scnt[0], cntr = scnt[1];
        // normal entries: one thread per candidate
        for (int i = tid; i < cntn; i += T) {
            unsigned e = listn[i];
            int row = e >> 16, k = e & 0xffff;
            float s = rescore(embed, sx, shes, row, k);
            atomicMax(&sbest[row],
                ((unsigned long long)ord_enc(s) << 32) | (unsigned)(K - 1 - k));
        }
        // rescan entries: one warp per 64-code slice, lane -> 2 codes
        for (int i = wid; i < cntr; i += 16) {
            unsigned e = listr[i];
            int row = e >> 16;
            int wg2 = (e >> 2) & 1, r2 = e & 3;
            int k0 = wg2 * 256 + lane * 8 + 2 * r2;
            float s0 = rescore(embed, sx, shes, row, k0);
            atomicMax(&sbest[row],
                ((unsigned long long)ord_enc(s0) << 32) | (unsigned)(K - 1 - k0));
            float s1 = rescore(embed, sx, shes, row, k0 + 1);
            atomicMax(&sbest[row],
                ((unsigned long long)ord_enc(s1) << 32) | (unsigned)(K - 1 - (k0 + 1)));
        }
    }
    __syncthreads();

    // outputs: gathered codebook rows (NHWC) + indices (float)
    #pragma unroll
    for (int t = 0; t < 4; t++) {
        int i = tid + t * T;
        int j = i >> 4, c4 = i & 15;
        int idx = (K - 1) - (int)(sbest[j] & 0xffffffffull);
        float4 v = *(const float4*)(embed + idx * D + (c4 << 2));
        *(float4*)(outq + ((size_t)(n0 + j)) * D + (c4 << 2)) = v;
    }
    if (outi && tid < MT)
        outi[n0 + tid] = (float)((K - 1) - (int)(sbest[tid] & 0xffffffffull));
}

// ---------------------------------------------------------------------------
extern "C" void kernel_launch(void* const* d_in, const int* in_sizes, int n_in,
                              void* d_out, int out_size) {
    const float* x = (const float*)d_in[0];
    const float* embed = (const float*)d_in[1];
    float* out = (float*)d_out;

    const int N = in_sizes[0] / D;
    float* outi = nullptr;
    if (out_size >= N * D + N) outi = out + (size_t)N * D;

    cudaFuncSetAttribute(vq_main, cudaFuncAttributeMaxDynamicSharedMemorySize, SMEM_SZ);
    vq_prep<<<K, D>>>(embed);
    vq_main<<<N / MT, T, SMEM_SZ>>>(x, embed, out, outi);
}

// round 17
// speedup vs baseline: 2.7038x; 1.0026x over previous
#include <cuda_runtime.h>
#include <cuda_fp16.h>
#include <cstdint>
#include <cfloat>

// VQ R17: fp16 hi-pass screen + per-slice top-2 certificate + list resolution.
// vs R16: prefetched B-frags and shes pairs, split (even/odd-j) top-2 chains
// -> breaks the latency chains that held tensor at 16%.

#define D    64
#define K    512
#define MT   128     // pixels per CTA
#define T    512     // threads per CTA (16 warps)

// SMEM layout (bytes)
#define SX_OFF    0                       // x tile fp32 [d][m]=[64][128]  32KB
#define BA_OFF    32768                   // codebook hi fp16 [512][128B]  64KB
#define SHES_OFF  98304                   // 512 f32
#define SAPX_OFF  100352                  // 128 u32 ordered approx-max
#define SBEST_OFF 100864                  // 128 u64 exact best
#define CNT_OFF   101888                  // [0]=normal count, [1]=rescan count
#define LISTN_OFF 101904                  // 1024 u32 (row<<16|code)
#define LISTR_OFF 106000                  // 1024 u32 (row<<16|wg<<2|r)
#define SMEM_SZ   110096

__device__ __half g_ea[K * D];   // fp16 hi split, permuted+swizzled rows
__device__ float  g_hes[K];      // 0.5*||e||^2
__device__ int    g_mhbits = 0;  // max hes as int bits

// ---------------- helpers ----------------
__device__ __forceinline__ uint32_t smem_u32(const void* p) {
    uint32_t a;
    asm("{ .reg .u64 t; cvta.to.shared.u64 t, %1; cvt.u32.u64 %0, t; }" : "=r"(a) : "l"(p));
    return a;
}
#define MMA_F16(c, a0, a1, a2, a3, b0, b1)                                       \
    asm volatile("mma.sync.aligned.m16n8k16.row.col.f32.f16.f16.f32 "            \
        "{%0,%1,%2,%3},{%4,%5,%6,%7},{%8,%9},{%0,%1,%2,%3};"                     \
        : "+f"((c)[0]), "+f"((c)[1]), "+f"((c)[2]), "+f"((c)[3])                  \
        : "r"(a0), "r"(a1), "r"(a2), "r"(a3), "r"(b0), "r"(b1))

__device__ __forceinline__ void cp16(uint32_t dst, const void* src) {
    asm volatile("cp.async.cg.shared.global [%0], [%1], 16;" :: "r"(dst), "l"(src) : "memory");
}
#define CP_COMMIT() asm volatile("cp.async.commit_group;" ::: "memory")
#define CP_WAIT(n)  asm volatile("cp.async.wait_group %0;" :: "n"(n) : "memory")

__device__ __forceinline__ uint32_t pack2(__half x, __half y) {
    __half2 h = __halves2half2(x, y);
    return *(uint32_t*)&h;
}
__device__ __forceinline__ unsigned ord_enc(float f) {
    unsigned u = __float_as_uint(f);
    return (u & 0x80000000u) ? ~u : (u | 0x80000000u);
}
__device__ __forceinline__ float ord_dec(unsigned u) {
    return __uint_as_float((u & 0x80000000u) ? (u & 0x7fffffffu) : ~u);
}

// exact fp32 rescore: x_p . e_k - 0.5||e_k||^2
__device__ __forceinline__ float rescore(const float* __restrict__ embed,
                                          const float* __restrict__ sx,
                                          const float* __restrict__ shes,
                                          int p, int k) {
    const float4* er = (const float4*)(embed + (size_t)k * D);
    float s0 = 0.f, s1 = 0.f, s2 = 0.f, s3 = 0.f;
    #pragma unroll 4
    for (int i = 0; i < 16; i++) {
        float4 e4 = er[i];
        s0 = fmaf(sx[(4 * i + 0) * MT + p], e4.x, s0);
        s1 = fmaf(sx[(4 * i + 1) * MT + p], e4.y, s1);
        s2 = fmaf(sx[(4 * i + 2) * MT + p], e4.z, s2);
        s3 = fmaf(sx[(4 * i + 3) * MT + p], e4.w, s3);
    }
    return ((s0 + s1) + (s2 + s3)) - shes[k];
}

// ---------------- prep: hi split codebook (permuted+swizzled), half norms ----
__global__ void vq_prep(const float* __restrict__ embed) {
    int k = blockIdx.x, d = threadIdx.x;
    float v = embed[k * D + d];
    __half a = __float2half_rn(v);
    int g = d >> 5, kk = d & 31;
    int rr = (kk >> 1) & 3, h = (kk >> 3) & 1, c = (kk >> 4) & 1, par = kk & 1;
    int slot = ((g << 2) + rr + ((k & 1) << 2)) & 7;
    g_ea[k * 64 + slot * 8 + ((c << 1) + h) * 2 + par] = a;
    float s = v * v;
    #pragma unroll
    for (int o = 16; o > 0; o >>= 1) s += __shfl_down_sync(0xffffffffu, s, o);
    __shared__ float ws[2];
    if ((d & 31) == 0) ws[d >> 5] = s;
    __syncthreads();
    if (d == 0) {
        float hes = 0.5f * (ws[0] + ws[1]);
        g_hes[k] = hes;
        atomicMax(&g_mhbits, __float_as_int(hes));
    }
}

// ---------------- main ----------------
__global__ void __launch_bounds__(T, 1) vq_main(const float* __restrict__ x,
                                                const float* __restrict__ embed,
                                                float* __restrict__ outq,
                                                float* __restrict__ outi) {
    extern __shared__ __align__(1024) char smem[];
    uint32_t sb = smem_u32(smem);
    const int tid = threadIdx.x, wid = tid >> 5, lane = tid & 31;
    const int q = lane >> 2, r = lane & 3;
    const int wm = wid & 7;                  // m-group (16 pixels)
    const int wg = wid >> 3;                 // n-half (codes [0,256)/[256,512))
    const int n0 = blockIdx.x * MT;
    const int b = n0 >> 12, hw0 = n0 & 4095;

    float* sx = (float*)(smem + SX_OFF);     // [d][128]
    float* shes = (float*)(smem + SHES_OFF);
    unsigned* sapx = (unsigned*)(smem + SAPX_OFF);
    unsigned long long* sbest = (unsigned long long*)(smem + SBEST_OFF);
    int* scnt = (int*)(smem + CNT_OFF);
    unsigned* listn = (unsigned*)(smem + LISTN_OFF);
    unsigned* listr = (unsigned*)(smem + LISTR_OFF);

    // stage hi codebook (64KB)
    #pragma unroll
    for (int t = 0; t < 8; t++) {
        int c = tid + t * T;
        cp16(sb + BA_OFF + c * 16, (const char*)g_ea + c * 16);
    }
    CP_COMMIT();

    // stage x tile: sx[c][j] = x[b][c][hw0+j]
    #pragma unroll
    for (int t = 0; t < 4; t++) {
        int i = tid + t * T;
        int c = i >> 5, j4 = (i & 31) << 2;
        float4 v = *(const float4*)(x + (((size_t)(b * D + c)) << 12) + hw0 + j4);
        *(float4*)(sx + c * MT + j4) = v;
    }
    shes[tid] = g_hes[tid];
    if (tid < MT) { sapx[tid] = 0u; sbest[tid] = 0ull; }
    if (tid < 2) scnt[tid] = 0;
    CP_WAIT(0);
    __syncthreads();

    // A hi fragments + ||x||^2 partials: rows m0+q, m0+q+8
    const int m0 = wm * 16;
    const int pa = m0 + q, pb = m0 + q + 8;
    uint32_t Aa[4][4];
    float xp0 = 0.f, xp1 = 0.f;
    #pragma unroll
    for (int cc = 0; cc < 4; cc++) {
        #pragma unroll
        for (int hh = 0; hh < 2; hh++) {
            int k = 16 * cc + 2 * r + 8 * hh;
            float f0a = sx[k * MT + pa], f1a = sx[(k + 1) * MT + pa];
            float f0b = sx[k * MT + pb], f1b = sx[(k + 1) * MT + pb];
            xp0 = fmaf(f0a, f0a, fmaf(f1a, f1a, xp0));
            xp1 = fmaf(f0b, f0b, fmaf(f1b, f1b, xp1));
            Aa[cc][2 * hh]     = pack2(__float2half_rn(f0a), __float2half_rn(f1a));
            Aa[cc][2 * hh + 1] = pack2(__float2half_rn(f0b), __float2half_rn(f1b));
        }
    }
    xp0 += __shfl_xor_sync(0xffffffffu, xp0, 1);
    xp0 += __shfl_xor_sync(0xffffffffu, xp0, 2);
    xp1 += __shfl_xor_sync(0xffffffffu, xp1, 1);
    xp1 += __shfl_xor_sync(0xffffffffu, xp1, 2);

    // ---- single screen pass: MMA + split top-2 chains per row ----
    // chains [0]=even j, [1]=odd j per row; merged after the loop
    float bA[2] = {-FLT_MAX, -FLT_MAX}, sA[2] = {-FLT_MAX, -FLT_MAX};
    float bB[2] = {-FLT_MAX, -FLT_MAX}, sB[2] = {-FLT_MAX, -FLT_MAX};
    int kA[2] = {0, 0}, kB[2] = {0, 0};

    #pragma unroll 1
    for (int tg = 0; tg < 8; tg++) {
        const int t0 = wg * 32 + tg * 4;

        // prefetch B fragments (8 x LDS.128) and shes pairs (4 x LDS.64)
        uint4 vB[4][2];
        float2 hv[4];
        #pragma unroll
        for (int j = 0; j < 4; j++) {
            int n = (t0 + j) * 8 + q;
            const char* rowa = smem + BA_OFF + n * 128;
            int so = r + ((n & 1) << 2);
            vB[j][0] = *(const uint4*)(rowa + (so & 7) * 16);
            vB[j][1] = *(const uint4*)(rowa + ((so + 4) & 7) * 16);
            hv[j] = *(const float2*)(shes + (t0 + j) * 8 + 2 * r);
        }

        // 16-MMA burst
        float acc[4][4];
        #pragma unroll
        for (int j = 0; j < 4; j++)
            #pragma unroll
            for (int c = 0; c < 4; c++) acc[j][c] = 0.0f;
        #pragma unroll
        for (int j = 0; j < 4; j++) {
            MMA_F16(acc[j], Aa[0][0], Aa[0][1], Aa[0][2], Aa[0][3], vB[j][0].x, vB[j][0].y);
            MMA_F16(acc[j], Aa[1][0], Aa[1][1], Aa[1][2], Aa[1][3], vB[j][0].z, vB[j][0].w);
            MMA_F16(acc[j], Aa[2][0], Aa[2][1], Aa[2][2], Aa[2][3], vB[j][1].x, vB[j][1].y);
            MMA_F16(acc[j], Aa[3][0], Aa[3][1], Aa[3][2], Aa[3][3], vB[j][1].z, vB[j][1].w);
        }

        // epilogue: independent chains (j&1) per row
        #pragma unroll
        for (int j = 0; j < 4; j++) {
            int ch = j & 1;
            int cb = (t0 + j) * 8 + 2 * r;
            {
                float v0 = acc[j][0] - hv[j].x, v1 = acc[j][1] - hv[j].y;
                float pm = fmaxf(v0, v1), pn = fminf(v0, v1);
                int kp = (v0 >= v1) ? cb : cb + 1;
                bool pr = pm > bA[ch];
                sA[ch] = pr ? fmaxf(bA[ch], pn) : fmaxf(sA[ch], pm);
                kA[ch] = pr ? kp : kA[ch];
                bA[ch] = fmaxf(bA[ch], pm);
            }
            {
                float v0 = acc[j][2] - hv[j].x, v1 = acc[j][3] - hv[j].y;
                float pm = fmaxf(v0, v1), pn = fminf(v0, v1);
                int kp = (v0 >= v1) ? cb : cb + 1;
                bool pr = pm > bB[ch];
                sB[ch] = pr ? fmaxf(bB[ch], pn) : fmaxf(sB[ch], pm);
                kB[ch] = pr ? kp : kB[ch];
                bB[ch] = fmaxf(bB[ch], pm);
            }
        }
    }

    // merge even/odd chains per row (ties -> smaller index)
    float best0, snd0, best1, snd1;
    int bk0, bk1;
    {
        bool pr = bA[1] > bA[0] || (bA[1] == bA[0] && kA[1] < kA[0]);
        best0 = pr ? bA[1] : bA[0];
        bk0   = pr ? kA[1] : kA[0];
        snd0  = fmaxf(fmaxf(sA[0], sA[1]), pr ? bA[0] : bA[1]);
    }
    {
        bool pr = bB[1] > bB[0] || (bB[1] == bB[0] && kB[1] < kB[0]);
        best1 = pr ? bB[1] : bB[0];
        bk1   = pr ? kB[1] : kB[0];
        snd1  = fmaxf(fmaxf(sB[0], sB[1]), pr ? bB[0] : bB[1]);
    }
    atomicMax(&sapx[pa], ord_enc(best0));
    atomicMax(&sapx[pb], ord_enc(best1));
    __syncthreads();

    // ---- per-slice certified push ----
    {
        float maxEn = sqrtf(2.0f * __int_as_float(g_mhbits));
        #pragma unroll
        for (int i = 0; i < 2; i++) {
            int row   = i ? pb : pa;
            float bst = i ? best1 : best0;
            float sn  = i ? snd1 : snd0;
            int   bk  = i ? bk1 : bk0;
            float xn2 = i ? xp1 : xp0;
            float smax = ord_dec(sapx[row]);
            float thr = smax - (2.2e-3f * sqrtf(xn2) * maxEn + 1e-5f);
            if (bst >= thr) {
                if (sn >= thr) {
                    int pos = atomicAdd(&scnt[1], 1);
                    listr[pos] = ((unsigned)row << 16) | (unsigned)((wg << 2) | r);
                } else {
                    int pos = atomicAdd(&scnt[0], 1);
                    listn[pos] = ((unsigned)row << 16) | (unsigned)bk;
                }
            }
        }
    }
    __syncthreads();

    // ---- exact resolution from lists ----
    {
        int cntn = scnt[0], cntr = scnt[1];
        for (int i = tid; i < cntn; i += T) {
            unsigned e = listn[i];
            int row = e >> 16, k = e & 0xffff;
            float s = rescore(embed, sx, shes, row, k);
            atomicMax(&sbest[row],
                ((unsigned long long)ord_enc(s) << 32) | (unsigned)(K - 1 - k));
        }
        for (int i = wid; i < cntr; i += 16) {
            unsigned e = listr[i];
            int row = e >> 16;
            int wg2 = (e >> 2) & 1, r2 = e & 3;
            int k0 = wg2 * 256 + lane * 8 + 2 * r2;
            float s0 = rescore(embed, sx, shes, row, k0);
            atomicMax(&sbest[row],
                ((unsigned long long)ord_enc(s0) << 32) | (unsigned)(K - 1 - k0));
            float s1 = rescore(embed, sx, shes, row, k0 + 1);
            atomicMax(&sbest[row],
                ((unsigned long long)ord_enc(s1) << 32) | (unsigned)(K - 1 - (k0 + 1)));
        }
    }
    __syncthreads();

    // outputs: gathered codebook rows (NHWC) + indices (float)
    #pragma unroll
    for (int t = 0; t < 4; t++) {
        int i = tid + t * T;
        int j = i >> 4, c4 = i & 15;
        int idx = (K - 1) - (int)(sbest[j] & 0xffffffffull);
        float4 v = *(const float4*)(embed + idx * D + (c4 << 2));
        *(float4*)(outq + ((size_t)(n0 + j)) * D + (c4 << 2)) = v;
    }
    if (outi && tid < MT)
        outi[n0 + tid] = (float)((K - 1) - (int)(sbest[tid] & 0xffffffffull));
}

// ---------------------------------------------------------------------------
extern "C" void kernel_launch(void* const* d_in, const int* in_sizes, int n_in,
                              void* d_out, int out_size) {
    const float* x = (const float*)d_in[0];
    const float* embed = (const float*)d_in[1];
    float* out = (float*)d_out;

    const int N = in_sizes[0] / D;
    float* outi = nullptr;
    if (out_size >= N * D + N) outi = out + (size_t)N * D;

    cudaFuncSetAttribute(vq_main, cudaFuncAttributeMaxDynamicSharedMemorySize, SMEM_SZ);
    vq_prep<<<K, D>>>(embed);
    vq_main<<<N / MT, T, SMEM_SZ>>>(x, embed, out, outi);
}